// round 1
// baseline (speedup 1.0000x reference)
#include <cuda_runtime.h>

#define NN 50000
#define NE 800000
#define D  96
#define LD 64

// ---------------- scratch (device globals: no allocation allowed) ----------
__device__ float g_agg[NN * D];          // per-layer aggregation buffer
__device__ float g_ha[NN * D];           // ping
__device__ float g_hb[NN * D];           // pong
__device__ int   g_cnt[3 * NN];          // per-rel in-degree counts (at src)
__device__ int2  g_elist[3][NE];         // per-rel compacted (src, dst)
__device__ int   g_enum[3];              // per-rel edge counts
__device__ int   g_is64;                 // 1 if indices are int64, 0 if int32

// ---------------- index dtype detection ------------------------------------
// int64 little-endian non-negative small values => every odd 32-bit word is 0.
// For int32 data those words are src-node ids (~0 with prob 1/50000 each).
__global__ void k_detect(const int* __restrict__ ei_as_i32) {
    if (blockIdx.x == 0 && threadIdx.x == 0) {
        int all0 = 1;
        for (int i = 0; i < 64; i++)
            if (ei_as_i32[2 * i + 1] != 0) all0 = 0;
        g_is64 = all0;
    }
}

// ---------------- zero scratch ----------------------------------------------
__global__ void k_zero_meta() {
    int i = blockIdx.x * blockDim.x + threadIdx.x;
    for (; i < 3 * NN; i += gridDim.x * blockDim.x) g_cnt[i] = 0;
    if (blockIdx.x == 0 && threadIdx.x < 3) g_enum[threadIdx.x] = 0;
}

__global__ void k_zero_agg() {
    int i = blockIdx.x * blockDim.x + threadIdx.x;
    const int tot = NN * D / 4;
    if (i < tot) ((float4*)g_agg)[i] = make_float4(0.f, 0.f, 0.f, 0.f);
}

// ---------------- edge compaction (all 3 relations in one pass) -------------
__global__ void k_compact(const void* __restrict__ ei_v, const void* __restrict__ et_v) {
    int e = blockIdx.x * blockDim.x + threadIdx.x;
    if (e >= NE) return;
    int is64 = g_is64;
    int t, src, dst;
    if (is64) {
        const long long* ei = (const long long*)ei_v;
        const long long* et = (const long long*)et_v;
        t   = (int)et[e];
        src = (int)ei[e];
        dst = (int)ei[NE + e];
    } else {
        const int* ei = (const int*)ei_v;
        const int* et = (const int*)et_v;
        t   = et[e];
        src = ei[e];
        dst = ei[NE + e];
    }
    if (t < 3) {
        int pos = atomicAdd(&g_enum[t], 1);
        g_elist[t][pos] = make_int2(src, dst);
        atomicAdd(&g_cnt[t * NN + src], 1);
    }
}

// ---------------- feature scatter: agg[src] += h[dst] ------------------------
// warp per edge, lanes 0..23 each move one float4 (96 floats) with a
// vector global reduction (sm_90+ red.global.add.v4.f32).
__global__ void k_scatter(const float* __restrict__ h, int rel) {
    int gtid  = blockIdx.x * blockDim.x + threadIdx.x;
    int warp  = gtid >> 5;
    int lane  = gtid & 31;
    int nwarp = (gridDim.x * blockDim.x) >> 5;
    int num   = g_enum[rel];
    const int2* __restrict__ lst = g_elist[rel];
    for (int e = warp; e < num; e += nwarp) {
        int2 ed = lst[e];
        if (lane < 24) {
            float4 v = ((const float4*)(h + (long)ed.y * D))[lane];
            float* dp = g_agg + (long)ed.x * D + lane * 4;
            asm volatile("red.global.add.v4.f32 [%0], {%1,%2,%3,%4};"
                         :: "l"(dp), "f"(v.x), "f"(v.y), "f"(v.z), "f"(v.w)
                         : "memory");
        }
    }
}

// ---------------- fused RGCN layer GEMM -------------------------------------
// out = relu( (agg/clip(cnt,1)) @ W  +  H @ Root  +  bias )
// Treated as [50000, 192] @ [192, 96]. Tile: 128 rows x 96 cols per block,
// 256 threads, each computing 4 rows x 12 cols (48 FFMA per 7 LDS).
__global__ void __launch_bounds__(256) k_gemm(
    const float* __restrict__ H,     // [NN, 96]
    const float* __restrict__ W,     // [96, 96] row-major (k-major)
    const float* __restrict__ R,     // [96, 96]
    const float* __restrict__ bias,  // [96]
    const int*   __restrict__ cnt,   // [NN]
    float* __restrict__ out)         // [NN, 96]
{
    __shared__ float Bs[16 * D];       // 16 k-rows x 96 cols (6 KB)
    __shared__ float As[128 * 17];     // 128 rows x 16 k (+1 pad) (8.5 KB)
    int tid  = threadIdx.x;
    int tx   = tid & 7;                // 8 col groups of 12
    int ry   = tid >> 3;               // 32 row groups of 4
    int row0 = blockIdx.x * 128;

    float acc[4][12];
#pragma unroll
    for (int j = 0; j < 12; j++) {
        float bv = bias[tx * 12 + j];
#pragma unroll
        for (int i = 0; i < 4; i++) acc[i][j] = bv;
    }

    for (int kc = 0; kc < 2 * D; kc += 16) {
        __syncthreads();
        // B chunk: 16 contiguous k-rows of W (k<96) or Root (k>=96) = 1536 floats
        {
            const float4* Bsrc = (const float4*)((kc < D) ? (W + kc * D)
                                                          : (R + (kc - D) * D));
            for (int id = tid; id < 384; id += 256) ((float4*)Bs)[id] = Bsrc[id];
        }
        // A chunk: 128 rows x 16 k = 512 float4, 2 per thread
#pragma unroll
        for (int l = 0; l < 2; l++) {
            int id  = tid * 2 + l;
            int r   = id >> 2;
            int k4  = (id & 3) * 4;
            int grow = row0 + r;
            float4 v = make_float4(0.f, 0.f, 0.f, 0.f);
            if (grow < NN) {
                int kg = kc + k4;
                if (kg < D) {
                    float ic = 1.0f / (float)max(cnt[grow], 1);
                    float4 a = *(const float4*)(g_agg + (long)grow * D + kg);
                    v = make_float4(a.x * ic, a.y * ic, a.z * ic, a.w * ic);
                } else {
                    v = *(const float4*)(H + (long)grow * D + (kg - D));
                }
            }
            float* ap = As + r * 17 + k4;
            ap[0] = v.x; ap[1] = v.y; ap[2] = v.z; ap[3] = v.w;
        }
        __syncthreads();
#pragma unroll
        for (int kk = 0; kk < 16; kk++) {
            float a[4];
#pragma unroll
            for (int i = 0; i < 4; i++) a[i] = As[(ry * 4 + i) * 17 + kk];
            float b[12];
#pragma unroll
            for (int jj = 0; jj < 3; jj++) {
                float4 bv = *(const float4*)&Bs[kk * D + tx * 12 + jj * 4];
                b[jj * 4 + 0] = bv.x; b[jj * 4 + 1] = bv.y;
                b[jj * 4 + 2] = bv.z; b[jj * 4 + 3] = bv.w;
            }
#pragma unroll
            for (int i = 0; i < 4; i++)
#pragma unroll
                for (int j = 0; j < 12; j++)
                    acc[i][j] = fmaf(a[i], b[j], acc[i][j]);
        }
    }

#pragma unroll
    for (int i = 0; i < 4; i++) {
        int grow = row0 + ry * 4 + i;
        if (grow < NN) {
#pragma unroll
            for (int jj = 0; jj < 3; jj++) {
                float4 o;
                o.x = fmaxf(acc[i][jj * 4 + 0], 0.f);
                o.y = fmaxf(acc[i][jj * 4 + 1], 0.f);
                o.z = fmaxf(acc[i][jj * 4 + 2], 0.f);
                o.w = fmaxf(acc[i][jj * 4 + 3], 0.f);
                *(float4*)(out + (long)grow * D + tx * 12 + jj * 4) = o;
            }
        }
    }
}

// ---------------- final linear: out = H @ lin_w + lin_b ----------------------
// [50000, 96] @ [96, 64]. Tile 128 x 64, thread tile 4 x 8.
__global__ void __launch_bounds__(256) k_final(
    const float* __restrict__ H,    // [NN, 96]
    const float* __restrict__ Wl,   // [96, 64]
    const float* __restrict__ bl,   // [64]
    float* __restrict__ out)        // [NN, 64]
{
    __shared__ float Bs[D * LD];     // full 96x64 (24 KB)
    __shared__ float As[128 * 17];
    int tid  = threadIdx.x;
    int tx   = tid & 7;              // 8 col groups of 8
    int ry   = tid >> 3;
    int row0 = blockIdx.x * 128;

    for (int id = tid; id < (D * LD) / 4; id += 256)
        ((float4*)Bs)[id] = ((const float4*)Wl)[id];

    float acc[4][8];
#pragma unroll
    for (int j = 0; j < 8; j++) {
        float bv = bl[tx * 8 + j];
#pragma unroll
        for (int i = 0; i < 4; i++) acc[i][j] = bv;
    }

    for (int kc = 0; kc < D; kc += 16) {
        __syncthreads();
#pragma unroll
        for (int l = 0; l < 2; l++) {
            int id  = tid * 2 + l;
            int r   = id >> 2;
            int k4  = (id & 3) * 4;
            int grow = row0 + r;
            float4 v = make_float4(0.f, 0.f, 0.f, 0.f);
            if (grow < NN)
                v = *(const float4*)(H + (long)grow * D + kc + k4);
            float* ap = As + r * 17 + k4;
            ap[0] = v.x; ap[1] = v.y; ap[2] = v.z; ap[3] = v.w;
        }
        __syncthreads();
#pragma unroll
        for (int kk = 0; kk < 16; kk++) {
            float a[4];
#pragma unroll
            for (int i = 0; i < 4; i++) a[i] = As[(ry * 4 + i) * 17 + kk];
            float b[8];
#pragma unroll
            for (int jj = 0; jj < 2; jj++) {
                float4 bv = *(const float4*)&Bs[(kc + kk) * LD + tx * 8 + jj * 4];
                b[jj * 4 + 0] = bv.x; b[jj * 4 + 1] = bv.y;
                b[jj * 4 + 2] = bv.z; b[jj * 4 + 3] = bv.w;
            }
#pragma unroll
            for (int i = 0; i < 4; i++)
#pragma unroll
                for (int j = 0; j < 8; j++)
                    acc[i][j] = fmaf(a[i], b[j], acc[i][j]);
        }
    }

#pragma unroll
    for (int i = 0; i < 4; i++) {
        int grow = row0 + ry * 4 + i;
        if (grow < NN) {
#pragma unroll
            for (int jj = 0; jj < 2; jj++) {
                float4 o;
                o.x = acc[i][jj * 4 + 0];
                o.y = acc[i][jj * 4 + 1];
                o.z = acc[i][jj * 4 + 2];
                o.w = acc[i][jj * 4 + 3];
                *(float4*)(out + (long)grow * LD + tx * 8 + jj * 4) = o;
            }
        }
    }
}

// ---------------- launch ------------------------------------------------------
extern "C" void kernel_launch(void* const* d_in, const int* in_sizes, int n_in,
                              void* d_out, int out_size) {
    const float* x     = (const float*)d_in[0];
    const void*  ei    = d_in[1];   // int64 or int32, detected on-device
    const void*  et    = d_in[2];
    const float* w1    = (const float*)d_in[3];   // [5,96,96]
    const float* root1 = (const float*)d_in[4];
    const float* b1    = (const float*)d_in[5];
    const float* w2    = (const float*)d_in[6];   // [5,96,96]
    const float* root2 = (const float*)d_in[7];
    const float* b2    = (const float*)d_in[8];
    const float* lw    = (const float*)d_in[9];   // [96,64]
    const float* lb    = (const float*)d_in[10];  // [64]
    float* out = (float*)d_out;

    float *ha, *hb;
    int* cnt;
    cudaGetSymbolAddress((void**)&ha,  g_ha);
    cudaGetSymbolAddress((void**)&hb,  g_hb);
    cudaGetSymbolAddress((void**)&cnt, g_cnt);

    const int ZG = (NN * D / 4 + 255) / 256;   // zero-agg grid
    const int MG = (NN + 127) / 128;           // GEMM grid (391)

    k_detect<<<1, 32>>>((const int*)ei);
    k_zero_meta<<<256, 256>>>();
    k_compact<<<(NE + 255) / 256, 256>>>(ei, et);

    // layer 0: rel 0, weights w1[0] / root1 / b1
    k_zero_agg<<<ZG, 256>>>();
    k_scatter<<<1184, 256>>>(x, 0);
    k_gemm<<<MG, 256>>>(x, w1, root1, b1, cnt, ha);

    // layer 1: rel 1, weights w2[1] / root2 / b2
    k_zero_agg<<<ZG, 256>>>();
    k_scatter<<<1184, 256>>>(ha, 1);
    k_gemm<<<MG, 256>>>(ha, w2 + 1 * D * D, root2, b2, cnt + NN, hb);

    // layer 2: rel 2, weights w2[2] / root2 / b2
    k_zero_agg<<<ZG, 256>>>();
    k_scatter<<<1184, 256>>>(hb, 2);
    k_gemm<<<MG, 256>>>(hb, w2 + 2 * D * D, root2, b2, cnt + 2 * NN, ha);

    // final linear
    k_final<<<MG, 256>>>(ha, lw, lb, out);
}

// round 3
// speedup vs baseline: 1.3062x; 1.3062x over previous
#include <cuda_runtime.h>

#define NN 50000
#define NE 800000
#define D  96
#define LD 64

// ---------------- scratch (device globals: no allocation allowed) ----------
__device__ float g_agg[NN * D];          // per-layer aggregation buffer (pre-normalized)
__device__ float g_ha[NN * D];           // ping
__device__ float g_hb[NN * D];           // pong
__device__ int   g_cnt[3 * NN];          // per-rel in-degree counts (at src)
__device__ int   g_base[3 * NN];         // per-rel CSR offsets (mutated by k_place)
__device__ int   g_edst[3][NE];          // per-rel dst node, CSR-sorted by src
__device__ int   g_is64;                 // 1 if indices are int64, 0 if int32

// ---------------- index dtype detection ------------------------------------
// int64 little-endian non-negative small node-ids => every odd 32-bit word 0.
__global__ void k_detect(const int* __restrict__ ei_as_i32) {
    if (blockIdx.x == 0 && threadIdx.x == 0) {
        int all0 = 1;
        for (int i = 0; i < 64; i++)
            if (ei_as_i32[2 * i + 1] != 0) all0 = 0;
        g_is64 = all0;
    }
}

__global__ void k_zero_cnt() {
    int i = blockIdx.x * blockDim.x + threadIdx.x;
    if (i < 3 * NN) g_cnt[i] = 0;
}

// ---------------- pass 1: histogram ----------------------------------------
__global__ void k_hist(const void* __restrict__ ei_v, const void* __restrict__ et_v) {
    int e = blockIdx.x * blockDim.x + threadIdx.x;
    if (e >= NE) return;
    int t, src;
    if (g_is64) {
        t   = (int)((const long long*)et_v)[e];
        src = (int)((const long long*)ei_v)[e];
    } else {
        t   = ((const int*)et_v)[e];
        src = ((const int*)ei_v)[e];
    }
    if (t < 3) atomicAdd(&g_cnt[t * NN + src], 1);
}

// ---------------- pass 2: exclusive scan per relation ------------------------
// 3 blocks (one per rel), 1024 threads, warp-shfl scan + carry.
__global__ void __launch_bounds__(1024) k_scan() {
    int rel  = blockIdx.x;
    int t    = threadIdx.x;
    int lane = t & 31, wid = t >> 5;
    __shared__ int wsum[32];
    __shared__ int carry;
    if (t == 0) carry = 0;
    __syncthreads();
    for (int off = 0; off < NN; off += 1024) {
        int i = off + t;
        int v = (i < NN) ? g_cnt[rel * NN + i] : 0;
        int s = v;
#pragma unroll
        for (int d = 1; d < 32; d <<= 1) {
            int y = __shfl_up_sync(0xffffffffu, s, d);
            if (lane >= d) s += y;
        }
        if (lane == 31) wsum[wid] = s;
        __syncthreads();
        if (wid == 0) {
            int ws = wsum[lane];
#pragma unroll
            for (int d = 1; d < 32; d <<= 1) {
                int y = __shfl_up_sync(0xffffffffu, ws, d);
                if (lane >= d) ws += y;
            }
            wsum[lane] = ws;
        }
        __syncthreads();
        int woff = (wid > 0) ? wsum[wid - 1] : 0;
        int incl = s + woff + carry;
        if (i < NN) g_base[rel * NN + i] = incl - v;   // exclusive
        __syncthreads();
        if (t == 1023) carry = incl;
        __syncthreads();
    }
}

// ---------------- pass 3: place edges (counting sort by src) -----------------
// After this, g_base[rel*NN+src] == segment END; start = end - cnt.
__global__ void k_place(const void* __restrict__ ei_v, const void* __restrict__ et_v) {
    int e = blockIdx.x * blockDim.x + threadIdx.x;
    if (e >= NE) return;
    int t, src, dst;
    if (g_is64) {
        t   = (int)((const long long*)et_v)[e];
        src = (int)((const long long*)ei_v)[e];
        dst = (int)((const long long*)ei_v)[NE + e];
    } else {
        t   = ((const int*)et_v)[e];
        src = ((const int*)ei_v)[e];
        dst = ((const int*)ei_v)[NE + e];
    }
    if (t < 3) {
        int pos = atomicAdd(&g_base[t * NN + src], 1);
        g_edst[t][pos] = dst;
    }
}

// ---------------- feature gather-aggregate: agg[n] = mean(h[dst in seg(n)]) --
// Warp per node. Lanes 0..23 each own one float4 (96 floats). No atomics.
// Writes zeros for degree-0 nodes (replaces any zero-fill pass).
__global__ void __launch_bounds__(256) k_aggregate(const float* __restrict__ h, int rel) {
    int gwarp = (blockIdx.x * blockDim.x + threadIdx.x) >> 5;
    int lane  = threadIdx.x & 31;
    if (gwarp >= NN || lane >= 24) return;
    int n     = gwarp;
    int c     = g_cnt[rel * NN + n];
    int end   = g_base[rel * NN + n];   // mutated by k_place => segment end
    int start = end - c;
    const int* __restrict__ el = g_edst[rel];
    float4 acc = make_float4(0.f, 0.f, 0.f, 0.f);
    for (int e = start; e < end; e++) {
        int dst = __ldg(&el[e]);         // uniform within warp -> broadcast
        float4 v = ((const float4*)(h + (size_t)dst * D))[lane];
        acc.x += v.x; acc.y += v.y; acc.z += v.z; acc.w += v.w;
    }
    float sc = 1.0f / (float)max(c, 1);
    ((float4*)(g_agg + (size_t)n * D))[lane] =
        make_float4(acc.x * sc, acc.y * sc, acc.z * sc, acc.w * sc);
}

// ---------------- fused RGCN layer GEMM -------------------------------------
// out = relu( agg @ W  +  H @ Root  +  bias )   (agg already mean-normalized)
// [50000, 192] @ [192, 96]. Tile 128 x 96, 256 threads, thread tile 4 x 12.
__global__ void __launch_bounds__(256) k_gemm(
    const float* __restrict__ H,     // [NN, 96]
    const float* __restrict__ W,     // [96, 96] k-major
    const float* __restrict__ R,     // [96, 96]
    const float* __restrict__ bias,  // [96]
    float* __restrict__ out)         // [NN, 96]
{
    __shared__ float Bs[16 * D];       // 6 KB
    __shared__ float As[128 * 17];     // 8.5 KB
    int tid  = threadIdx.x;
    int tx   = tid & 7;                // 8 col groups of 12
    int ry   = tid >> 3;               // 32 row groups of 4
    int row0 = blockIdx.x * 128;

    float acc[4][12];
#pragma unroll
    for (int j = 0; j < 12; j++) {
        float bv = bias[tx * 12 + j];
#pragma unroll
        for (int i = 0; i < 4; i++) acc[i][j] = bv;
    }

    for (int kc = 0; kc < 2 * D; kc += 16) {
        __syncthreads();
        {
            const float4* Bsrc = (const float4*)((kc < D) ? (W + kc * D)
                                                          : (R + (kc - D) * D));
            for (int id = tid; id < 384; id += 256) ((float4*)Bs)[id] = Bsrc[id];
        }
#pragma unroll
        for (int l = 0; l < 2; l++) {
            int id   = tid * 2 + l;
            int r    = id >> 2;
            int k4   = (id & 3) * 4;
            int grow = row0 + r;
            float4 v = make_float4(0.f, 0.f, 0.f, 0.f);
            if (grow < NN) {
                int kg = kc + k4;
                v = (kg < D) ? *(const float4*)(g_agg + (size_t)grow * D + kg)
                             : *(const float4*)(H + (size_t)grow * D + (kg - D));
            }
            float* ap = As + r * 17 + k4;
            ap[0] = v.x; ap[1] = v.y; ap[2] = v.z; ap[3] = v.w;
        }
        __syncthreads();
#pragma unroll
        for (int kk = 0; kk < 16; kk++) {
            float a[4];
#pragma unroll
            for (int i = 0; i < 4; i++) a[i] = As[(ry * 4 + i) * 17 + kk];
            float b[12];
#pragma unroll
            for (int jj = 0; jj < 3; jj++) {
                float4 bv = *(const float4*)&Bs[kk * D + tx * 12 + jj * 4];
                b[jj * 4 + 0] = bv.x; b[jj * 4 + 1] = bv.y;
                b[jj * 4 + 2] = bv.z; b[jj * 4 + 3] = bv.w;
            }
#pragma unroll
            for (int i = 0; i < 4; i++)
#pragma unroll
                for (int j = 0; j < 12; j++)
                    acc[i][j] = fmaf(a[i], b[j], acc[i][j]);
        }
    }

#pragma unroll
    for (int i = 0; i < 4; i++) {
        int grow = row0 + ry * 4 + i;
        if (grow < NN) {
#pragma unroll
            for (int jj = 0; jj < 3; jj++) {
                float4 o;
                o.x = fmaxf(acc[i][jj * 4 + 0], 0.f);
                o.y = fmaxf(acc[i][jj * 4 + 1], 0.f);
                o.z = fmaxf(acc[i][jj * 4 + 2], 0.f);
                o.w = fmaxf(acc[i][jj * 4 + 3], 0.f);
                *(float4*)(out + (size_t)grow * D + tx * 12 + jj * 4) = o;
            }
        }
    }
}

// ---------------- final linear: out = H @ lin_w + lin_b ----------------------
__global__ void __launch_bounds__(256) k_final(
    const float* __restrict__ H,    // [NN, 96]
    const float* __restrict__ Wl,   // [96, 64]
    const float* __restrict__ bl,   // [64]
    float* __restrict__ out)        // [NN, 64]
{
    __shared__ float Bs[D * LD];     // 24 KB
    __shared__ float As[128 * 17];
    int tid  = threadIdx.x;
    int tx   = tid & 7;
    int ry   = tid >> 3;
    int row0 = blockIdx.x * 128;

    for (int id = tid; id < (D * LD) / 4; id += 256)
        ((float4*)Bs)[id] = ((const float4*)Wl)[id];

    float acc[4][8];
#pragma unroll
    for (int j = 0; j < 8; j++) {
        float bv = bl[tx * 8 + j];
#pragma unroll
        for (int i = 0; i < 4; i++) acc[i][j] = bv;
    }

    for (int kc = 0; kc < D; kc += 16) {
        __syncthreads();
#pragma unroll
        for (int l = 0; l < 2; l++) {
            int id   = tid * 2 + l;
            int r    = id >> 2;
            int k4   = (id & 3) * 4;
            int grow = row0 + r;
            float4 v = make_float4(0.f, 0.f, 0.f, 0.f);
            if (grow < NN)
                v = *(const float4*)(H + (size_t)grow * D + kc + k4);
            float* ap = As + r * 17 + k4;
            ap[0] = v.x; ap[1] = v.y; ap[2] = v.z; ap[3] = v.w;
        }
        __syncthreads();
#pragma unroll
        for (int kk = 0; kk < 16; kk++) {
            float a[4];
#pragma unroll
            for (int i = 0; i < 4; i++) a[i] = As[(ry * 4 + i) * 17 + kk];
            float b[8];
#pragma unroll
            for (int jj = 0; jj < 2; jj++) {
                float4 bv = *(const float4*)&Bs[(kc + kk) * LD + tx * 8 + jj * 4];
                b[jj * 4 + 0] = bv.x; b[jj * 4 + 1] = bv.y;
                b[jj * 4 + 2] = bv.z; b[jj * 4 + 3] = bv.w;
            }
#pragma unroll
            for (int i = 0; i < 4; i++)
#pragma unroll
                for (int j = 0; j < 8; j++)
                    acc[i][j] = fmaf(a[i], b[j], acc[i][j]);
        }
    }

#pragma unroll
    for (int i = 0; i < 4; i++) {
        int grow = row0 + ry * 4 + i;
        if (grow < NN) {
#pragma unroll
            for (int jj = 0; jj < 2; jj++) {
                float4 o;
                o.x = acc[i][jj * 4 + 0];
                o.y = acc[i][jj * 4 + 1];
                o.z = acc[i][jj * 4 + 2];
                o.w = acc[i][jj * 4 + 3];
                *(float4*)(out + (size_t)grow * LD + tx * 8 + jj * 4) = o;
            }
        }
    }
}

// ---------------- launch ------------------------------------------------------
extern "C" void kernel_launch(void* const* d_in, const int* in_sizes, int n_in,
                              void* d_out, int out_size) {
    const float* x     = (const float*)d_in[0];
    const void*  ei    = d_in[1];
    const void*  et    = d_in[2];
    const float* w1    = (const float*)d_in[3];
    const float* root1 = (const float*)d_in[4];
    const float* b1    = (const float*)d_in[5];
    const float* w2    = (const float*)d_in[6];
    const float* root2 = (const float*)d_in[7];
    const float* b2    = (const float*)d_in[8];
    const float* lw    = (const float*)d_in[9];
    const float* lb    = (const float*)d_in[10];
    float* out = (float*)d_out;

    float *ha, *hb;
    cudaGetSymbolAddress((void**)&ha, g_ha);
    cudaGetSymbolAddress((void**)&hb, g_hb);

    const int EG = (NE + 255) / 256;           // edge-parallel grid
    const int MG = (NN + 127) / 128;           // GEMM grid (391)
    const int SG = (NN * 32 + 255) / 256;      // warp-per-node grid (6250)

    k_detect<<<1, 32>>>((const int*)ei);
    k_zero_cnt<<<(3 * NN + 255) / 256, 256>>>();
    k_hist <<<EG, 256>>>(ei, et);
    k_scan <<<3, 1024>>>();
    k_place<<<EG, 256>>>(ei, et);

    // layer 0: rel 0, weights w1[0] / root1 / b1
    k_aggregate<<<SG, 256>>>(x, 0);
    k_gemm<<<MG, 256>>>(x, w1, root1, b1, ha);

    // layer 1: rel 1, weights w2[1] / root2 / b2
    k_aggregate<<<SG, 256>>>(ha, 1);
    k_gemm<<<MG, 256>>>(ha, w2 + 1 * D * D, root2, b2, hb);

    // layer 2: rel 2, weights w2[2] / root2 / b2
    k_aggregate<<<SG, 256>>>(hb, 2);
    k_gemm<<<MG, 256>>>(hb, w2 + 2 * D * D, root2, b2, ha);

    // final linear
    k_final<<<MG, 256>>>(ha, lw, lb, out);
}

// round 4
// speedup vs baseline: 1.6837x; 1.2890x over previous
#include <cuda_runtime.h>

#define NN 50000
#define NE 800000
#define D  96
#define LD 64
#define CHUNK 2048
#define NCH 25            // ceil(NN / CHUNK)

// ---------------- scratch (device globals: no allocation allowed) ----------
__device__ float g_agg[NN * D];
__device__ float g_ha[NN * D];
__device__ float g_hb[NN * D];
__device__ int   g_cnt[3 * NN];
__device__ int   g_base[3 * NN];
__device__ int   g_bsum[3 * NCH];
__device__ int   g_edst[3][NE];
__device__ int   g_is64;

// ---------------- index dtype detection ------------------------------------
__global__ void k_detect(const int* __restrict__ ei_as_i32) {
    if (blockIdx.x == 0 && threadIdx.x == 0) {
        int all0 = 1;
        for (int i = 0; i < 64; i++)
            if (ei_as_i32[2 * i + 1] != 0) all0 = 0;
        g_is64 = all0;
    }
}

__global__ void k_zero_cnt() {
    int i = blockIdx.x * blockDim.x + threadIdx.x;
    if (i < 3 * NN) g_cnt[i] = 0;
}

// ---------------- pass 1: histogram ----------------------------------------
__global__ void k_hist(const void* __restrict__ ei_v, const void* __restrict__ et_v) {
    int e = blockIdx.x * blockDim.x + threadIdx.x;
    if (e >= NE) return;
    int t, src;
    if (g_is64) {
        t   = (int)((const long long*)et_v)[e];
        src = (int)((const long long*)ei_v)[e];
    } else {
        t   = ((const int*)et_v)[e];
        src = ((const int*)ei_v)[e];
    }
    if (t < 3) atomicAdd(&g_cnt[t * NN + src], 1);
}

// ---------------- pass 2a: chunk-local exclusive scan (75 blocks) ------------
__global__ void __launch_bounds__(512) k_scan1() {
    int rel  = blockIdx.x / NCH;
    int blk  = blockIdx.x % NCH;
    int base = rel * NN;
    int off0 = blk * CHUNK;
    int t    = threadIdx.x;
    int lane = t & 31, wid = t >> 5;
    __shared__ int wsum[16];
    __shared__ int carry;
    if (t == 0) carry = 0;
    __syncthreads();
#pragma unroll
    for (int sub = 0; sub < 4; sub++) {
        int i = off0 + sub * 512 + t;
        int v = (i < NN) ? g_cnt[base + i] : 0;
        int s = v;
#pragma unroll
        for (int d = 1; d < 32; d <<= 1) {
            int y = __shfl_up_sync(0xffffffffu, s, d);
            if (lane >= d) s += y;
        }
        if (lane == 31) wsum[wid] = s;
        __syncthreads();
        if (wid == 0) {
            int ws = (lane < 16) ? wsum[lane] : 0;
#pragma unroll
            for (int d = 1; d < 16; d <<= 1) {
                int y = __shfl_up_sync(0xffffffffu, ws, d);
                if (lane >= d) ws += y;
            }
            if (lane < 16) wsum[lane] = ws;
        }
        __syncthreads();
        int woff = (wid > 0) ? wsum[wid - 1] : 0;
        int incl = s + woff + carry;
        if (i < NN) g_base[base + i] = incl - v;     // chunk-local exclusive
        __syncthreads();
        if (t == 511) carry = incl;
        __syncthreads();
    }
    if (t == 0) g_bsum[blockIdx.x] = carry;          // chunk total
}

// ---------------- pass 2b: scan chunk totals (1 block, warp per rel) ---------
__global__ void k_scan2() {
    int rel = threadIdx.x >> 5, lane = threadIdx.x & 31;
    if (rel < 3) {
        int v = (lane < NCH) ? g_bsum[rel * NCH + lane] : 0;
        int s = v;
#pragma unroll
        for (int d = 1; d < 32; d <<= 1) {
            int y = __shfl_up_sync(0xffffffffu, s, d);
            if (lane >= d) s += y;
        }
        if (lane < NCH) g_bsum[rel * NCH + lane] = s - v;   // exclusive
    }
}

// ---------------- pass 2c: apply chunk offsets ------------------------------
__global__ void k_scan3() {
    int i = blockIdx.x * blockDim.x + threadIdx.x;
    if (i >= 3 * NN) return;
    int rel = i / NN;
    int j   = i - rel * NN;
    g_base[i] += g_bsum[rel * NCH + j / CHUNK];
}

// ---------------- pass 3: place edges (counting sort by src) -----------------
// After this, g_base[rel*NN+src] == segment END; start = end - cnt.
__global__ void k_place(const void* __restrict__ ei_v, const void* __restrict__ et_v) {
    int e = blockIdx.x * blockDim.x + threadIdx.x;
    if (e >= NE) return;
    int t, src, dst;
    if (g_is64) {
        t   = (int)((const long long*)et_v)[e];
        src = (int)((const long long*)ei_v)[e];
        dst = (int)((const long long*)ei_v)[NE + e];
    } else {
        t   = ((const int*)et_v)[e];
        src = ((const int*)ei_v)[e];
        dst = ((const int*)ei_v)[NE + e];
    }
    if (t < 3) {
        int pos = atomicAdd(&g_base[t * NN + src], 1);
        g_edst[t][pos] = dst;
    }
}

// ---------------- gather-aggregate: agg[n] = mean(h[dst in seg(n)]) ----------
__global__ void __launch_bounds__(256) k_aggregate(const float* __restrict__ h, int rel) {
    int gwarp = (blockIdx.x * blockDim.x + threadIdx.x) >> 5;
    int lane  = threadIdx.x & 31;
    if (gwarp >= NN || lane >= 24) return;
    int n     = gwarp;
    int c     = g_cnt[rel * NN + n];
    int end   = g_base[rel * NN + n];
    int start = end - c;
    const int* __restrict__ el = g_edst[rel];
    float4 acc = make_float4(0.f, 0.f, 0.f, 0.f);
    for (int e = start; e < end; e++) {
        int dst = __ldg(&el[e]);
        float4 v = ((const float4*)(h + (size_t)dst * D))[lane];
        acc.x += v.x; acc.y += v.y; acc.z += v.z; acc.w += v.w;
    }
    float sc = 1.0f / (float)max(c, 1);
    ((float4*)(g_agg + (size_t)n * D))[lane] =
        make_float4(acc.x * sc, acc.y * sc, acc.z * sc, acc.w * sc);
}

// ---------------- packed f32x2 helpers ---------------------------------------
__device__ __forceinline__ unsigned long long pack_dup(float a) {
    unsigned long long p;
    asm("mov.b64 %0, {%1, %1};" : "=l"(p) : "f"(a));
    return p;
}
__device__ __forceinline__ unsigned long long pack2(float a, float b) {
    unsigned long long p;
    asm("mov.b64 %0, {%1, %2};" : "=l"(p) : "f"(a), "f"(b));
    return p;
}
__device__ __forceinline__ void fma2(unsigned long long& d,
                                     unsigned long long a, unsigned long long b) {
    asm("fma.rn.f32x2 %0, %1, %2, %0;" : "+l"(d) : "l"(a), "l"(b));
}
__device__ __forceinline__ void unpack2(unsigned long long p, float& lo, float& hi) {
    asm("mov.b64 {%0, %1}, %2;" : "=f"(lo), "=f"(hi) : "l"(p));
}

// ---------------- fused RGCN layer GEMM (f32x2) ------------------------------
// out = relu( agg @ W  +  H @ Root  +  bias ).  [50000,192]@[192,96].
// Tile 128x96, 256 threads, thread tile 4 rows x 12 cols (6 f32x2 pairs).
__global__ void __launch_bounds__(256) k_gemm(
    const float* __restrict__ H,
    const float* __restrict__ W,
    const float* __restrict__ R,
    const float* __restrict__ bias,
    float* __restrict__ out)
{
    __shared__ float Bs[16 * D];
    __shared__ float As[128 * 17];
    int tid  = threadIdx.x;
    int tx   = tid & 7;
    int ry   = tid >> 3;
    int row0 = blockIdx.x * 128;

    unsigned long long acc2[4][6];
#pragma unroll
    for (int jp = 0; jp < 6; jp++) {
        float2 bv = *(const float2*)&bias[tx * 12 + jp * 2];
        unsigned long long p = pack2(bv.x, bv.y);
#pragma unroll
        for (int i = 0; i < 4; i++) acc2[i][jp] = p;
    }

    for (int kc = 0; kc < 2 * D; kc += 16) {
        __syncthreads();
        {
            const float4* Bsrc = (const float4*)((kc < D) ? (W + kc * D)
                                                          : (R + (kc - D) * D));
            for (int id = tid; id < 384; id += 256) ((float4*)Bs)[id] = Bsrc[id];
        }
#pragma unroll
        for (int l = 0; l < 2; l++) {
            int id   = tid * 2 + l;
            int r    = id >> 2;
            int k4   = (id & 3) * 4;
            int grow = row0 + r;
            float4 v = make_float4(0.f, 0.f, 0.f, 0.f);
            if (grow < NN) {
                int kg = kc + k4;
                v = (kg < D) ? *(const float4*)(g_agg + (size_t)grow * D + kg)
                             : *(const float4*)(H + (size_t)grow * D + (kg - D));
            }
            float* ap = As + r * 17 + k4;
            ap[0] = v.x; ap[1] = v.y; ap[2] = v.z; ap[3] = v.w;
        }
        __syncthreads();
#pragma unroll
        for (int kk = 0; kk < 16; kk++) {
            unsigned long long a2[4];
#pragma unroll
            for (int i = 0; i < 4; i++)
                a2[i] = pack_dup(As[(ry * 4 + i) * 17 + kk]);
            const float* bp = &Bs[kk * D + tx * 12];
            ulonglong2 b01 = *(const ulonglong2*)(bp + 0);
            ulonglong2 b23 = *(const ulonglong2*)(bp + 4);
            ulonglong2 b45 = *(const ulonglong2*)(bp + 8);
            unsigned long long b2[6] = {b01.x, b01.y, b23.x, b23.y, b45.x, b45.y};
#pragma unroll
            for (int i = 0; i < 4; i++)
#pragma unroll
                for (int jp = 0; jp < 6; jp++)
                    fma2(acc2[i][jp], a2[i], b2[jp]);
        }
    }

#pragma unroll
    for (int i = 0; i < 4; i++) {
        int grow = row0 + ry * 4 + i;
        if (grow < NN) {
            float o[12];
#pragma unroll
            for (int jp = 0; jp < 6; jp++)
                unpack2(acc2[i][jp], o[jp * 2], o[jp * 2 + 1]);
#pragma unroll
            for (int jj = 0; jj < 3; jj++) {
                float4 q;
                q.x = fmaxf(o[jj * 4 + 0], 0.f);
                q.y = fmaxf(o[jj * 4 + 1], 0.f);
                q.z = fmaxf(o[jj * 4 + 2], 0.f);
                q.w = fmaxf(o[jj * 4 + 3], 0.f);
                *(float4*)(out + (size_t)grow * D + tx * 12 + jj * 4) = q;
            }
        }
    }
}

// ---------------- final linear (f32x2): out = H @ lin_w + lin_b --------------
__global__ void __launch_bounds__(256) k_final(
    const float* __restrict__ H,
    const float* __restrict__ Wl,
    const float* __restrict__ bl,
    float* __restrict__ out)
{
    __shared__ float Bs[D * LD];
    __shared__ float As[128 * 17];
    int tid  = threadIdx.x;
    int tx   = tid & 7;
    int ry   = tid >> 3;
    int row0 = blockIdx.x * 128;

    for (int id = tid; id < (D * LD) / 4; id += 256)
        ((float4*)Bs)[id] = ((const float4*)Wl)[id];

    unsigned long long acc2[4][4];
#pragma unroll
    for (int jp = 0; jp < 4; jp++) {
        float2 bv = *(const float2*)&bl[tx * 8 + jp * 2];
        unsigned long long p = pack2(bv.x, bv.y);
#pragma unroll
        for (int i = 0; i < 4; i++) acc2[i][jp] = p;
    }

    for (int kc = 0; kc < D; kc += 16) {
        __syncthreads();
#pragma unroll
        for (int l = 0; l < 2; l++) {
            int id   = tid * 2 + l;
            int r    = id >> 2;
            int k4   = (id & 3) * 4;
            int grow = row0 + r;
            float4 v = make_float4(0.f, 0.f, 0.f, 0.f);
            if (grow < NN)
                v = *(const float4*)(H + (size_t)grow * D + kc + k4);
            float* ap = As + r * 17 + k4;
            ap[0] = v.x; ap[1] = v.y; ap[2] = v.z; ap[3] = v.w;
        }
        __syncthreads();
#pragma unroll
        for (int kk = 0; kk < 16; kk++) {
            unsigned long long a2[4];
#pragma unroll
            for (int i = 0; i < 4; i++)
                a2[i] = pack_dup(As[(ry * 4 + i) * 17 + kk]);
            const float* bp = &Bs[(kc + kk) * LD + tx * 8];
            ulonglong2 b01 = *(const ulonglong2*)(bp + 0);
            ulonglong2 b23 = *(const ulonglong2*)(bp + 4);
            unsigned long long b2[4] = {b01.x, b01.y, b23.x, b23.y};
#pragma unroll
            for (int i = 0; i < 4; i++)
#pragma unroll
                for (int jp = 0; jp < 4; jp++)
                    fma2(acc2[i][jp], a2[i], b2[jp]);
        }
    }

#pragma unroll
    for (int i = 0; i < 4; i++) {
        int grow = row0 + ry * 4 + i;
        if (grow < NN) {
            float o[8];
#pragma unroll
            for (int jp = 0; jp < 4; jp++)
                unpack2(acc2[i][jp], o[jp * 2], o[jp * 2 + 1]);
#pragma unroll
            for (int jj = 0; jj < 2; jj++) {
                float4 q;
                q.x = o[jj * 4 + 0];
                q.y = o[jj * 4 + 1];
                q.z = o[jj * 4 + 2];
                q.w = o[jj * 4 + 3];
                *(float4*)(out + (size_t)grow * LD + tx * 8 + jj * 4) = q;
            }
        }
    }
}

// ---------------- launch ------------------------------------------------------
extern "C" void kernel_launch(void* const* d_in, const int* in_sizes, int n_in,
                              void* d_out, int out_size) {
    const float* x     = (const float*)d_in[0];
    const void*  ei    = d_in[1];
    const void*  et    = d_in[2];
    const float* w1    = (const float*)d_in[3];
    const float* root1 = (const float*)d_in[4];
    const float* b1    = (const float*)d_in[5];
    const float* w2    = (const float*)d_in[6];
    const float* root2 = (const float*)d_in[7];
    const float* b2    = (const float*)d_in[8];
    const float* lw    = (const float*)d_in[9];
    const float* lb    = (const float*)d_in[10];
    float* out = (float*)d_out;

    float *ha, *hb;
    cudaGetSymbolAddress((void**)&ha, g_ha);
    cudaGetSymbolAddress((void**)&hb, g_hb);

    const int EG = (NE + 255) / 256;
    const int MG = (NN + 127) / 128;
    const int SG = (NN * 32 + 255) / 256;

    k_detect<<<1, 32>>>((const int*)ei);
    k_zero_cnt<<<(3 * NN + 255) / 256, 256>>>();
    k_hist <<<EG, 256>>>(ei, et);
    k_scan1<<<3 * NCH, 512>>>();
    k_scan2<<<1, 128>>>();
    k_scan3<<<(3 * NN + 255) / 256, 256>>>();
    k_place<<<EG, 256>>>(ei, et);

    k_aggregate<<<SG, 256>>>(x, 0);
    k_gemm<<<MG, 256>>>(x, w1, root1, b1, ha);

    k_aggregate<<<SG, 256>>>(ha, 1);
    k_gemm<<<MG, 256>>>(ha, w2 + 1 * D * D, root2, b2, hb);

    k_aggregate<<<SG, 256>>>(hb, 2);
    k_gemm<<<MG, 256>>>(hb, w2 + 2 * D * D, root2, b2, ha);

    k_final<<<MG, 256>>>(ha, lw, lb, out);
}